// round 1
// baseline (speedup 1.0000x reference)
#include <cuda_runtime.h>
#include <cuda_bf16.h>

// Problem constants
#define NN   10000          // nodes
#define EE   20000          // edges (without self loops)
#define ETOT 30000          // edges + self loops
#define HH   12             // heads
#define CC   768            // per-head dim (== input feature dim)
#define HC   9216           // H*C
#define GGR  64             // graphs

// ---------------- device scratch (static globals; no runtime alloc) --------
__device__ float g_h[(size_t)NN * HC];     // per-layer node features [N, H*C]
__device__ float g_x2[NN * CC];            // layer-1 output / layer-2 input
__device__ float g_y[NN * CC];             // layer-2 output
__device__ float g_s[NN * HH];             // alpha_src per node/head
__device__ float g_d[NN * HH];             // alpha_dst per node/head
__device__ float g_alpha[ETOT * HH];       // softmax weights, by sorted edge pos
__device__ int   g_indeg[NN];
__device__ int   g_rowptr[NN + 1];
__device__ int   g_fill[NN];
__device__ int   g_ssrc[ETOT];             // source node per CSR position
__device__ float g_pool[GGR * CC];
__device__ int   g_cnt[GGR];

// ---------------- CSR build ------------------------------------------------
__global__ void zero_build_kernel() {
    int i = blockIdx.x * blockDim.x + threadIdx.x;
    if (i < NN) { g_indeg[i] = 0; g_fill[i] = 0; }
}

__global__ void count_deg_kernel(const int* __restrict__ edge_index) {
    int e = blockIdx.x * blockDim.x + threadIdx.x;
    if (e >= ETOT) return;
    int dst = (e < EE) ? edge_index[EE + e] : (e - EE);
    atomicAdd(&g_indeg[dst], 1);
}

__global__ void scan_kernel() {
    __shared__ int sd[1024];
    __shared__ int soff;
    int t = threadIdx.x;
    if (t == 0) { soff = 0; g_rowptr[0] = 0; }
    __syncthreads();
    for (int base = 0; base < NN; base += 1024) {
        int i = base + t;
        int v = (i < NN) ? g_indeg[i] : 0;
        sd[t] = v;
        __syncthreads();
        for (int off = 1; off < 1024; off <<= 1) {
            int tmp = (t >= off) ? sd[t - off] : 0;
            __syncthreads();
            sd[t] += tmp;
            __syncthreads();
        }
        if (i < NN) g_rowptr[i + 1] = soff + sd[t];
        __syncthreads();
        if (t == 0) soff += sd[1023];
        __syncthreads();
    }
}

__global__ void fill_csr_kernel(const int* __restrict__ edge_index) {
    int e = blockIdx.x * blockDim.x + threadIdx.x;
    if (e >= ETOT) return;
    int src = (e < EE) ? edge_index[e]      : (e - EE);
    int dst = (e < EE) ? edge_index[EE + e] : (e - EE);
    int pos = g_rowptr[dst] + atomicAdd(&g_fill[dst], 1);
    g_ssrc[pos] = src;
}

// ---------------- SGEMM: C[M,Nc] = A[M,K] * B[K,Nc] ------------------------
#define BM 128
#define BN 128
#define BK 8
#define TM 8
#define TN 8

__global__ __launch_bounds__(256)
void sgemm_kernel(const float* __restrict__ A, const float* __restrict__ B,
                  float* __restrict__ Cm, int M, int K, int Nc) {
    __shared__ float As[BK][BM];
    __shared__ float Bs[BK][BN];
    int tid  = threadIdx.x;
    int brow = blockIdx.y * BM;
    int bcol = blockIdx.x * BN;

    int arow = tid >> 1;          // 0..127
    int acol = (tid & 1) * 4;     // 0 or 4
    int browb = tid >> 5;         // 0..7
    int bcolb = (tid & 31) * 4;   // 0..124

    int ty = tid >> 4;            // 0..15
    int tx = tid & 15;            // 0..15

    float acc[TM][TN];
#pragma unroll
    for (int i = 0; i < TM; i++)
#pragma unroll
        for (int j = 0; j < TN; j++) acc[i][j] = 0.f;

    for (int k0 = 0; k0 < K; k0 += BK) {
        float4 av = make_float4(0.f, 0.f, 0.f, 0.f);
        if (brow + arow < M)
            av = *(const float4*)&A[(size_t)(brow + arow) * K + k0 + acol];
        As[acol + 0][arow] = av.x;
        As[acol + 1][arow] = av.y;
        As[acol + 2][arow] = av.z;
        As[acol + 3][arow] = av.w;
        *(float4*)&Bs[browb][bcolb] =
            *(const float4*)&B[(size_t)(k0 + browb) * Nc + bcol + bcolb];
        __syncthreads();
        float ar[TM], br[TN];
#pragma unroll
        for (int kk = 0; kk < BK; kk++) {
#pragma unroll
            for (int i = 0; i < TM; i++) ar[i] = As[kk][ty * TM + i];
#pragma unroll
            for (int j = 0; j < TN; j++) br[j] = Bs[kk][tx * TN + j];
#pragma unroll
            for (int i = 0; i < TM; i++)
#pragma unroll
                for (int j = 0; j < TN; j++) acc[i][j] += ar[i] * br[j];
        }
        __syncthreads();
    }
#pragma unroll
    for (int i = 0; i < TM; i++) {
        int r = brow + ty * TM + i;
        if (r < M) {
#pragma unroll
            for (int j = 0; j < TN; j += 4) {
                *(float4*)&Cm[(size_t)r * Nc + bcol + tx * TN + j] =
                    make_float4(acc[i][j], acc[i][j + 1], acc[i][j + 2], acc[i][j + 3]);
            }
        }
    }
}

// ---------------- attention scores s,d (one warp per node/head) ------------
__global__ void scores_kernel(const float* __restrict__ a_src,
                              const float* __restrict__ a_dst) {
    int gw   = (blockIdx.x * blockDim.x + threadIdx.x) >> 5;
    int lane = threadIdx.x & 31;
    if (gw >= NN * HH) return;
    int n = gw / HH, h = gw % HH;
    const float* hp = &g_h[(size_t)n * HC + h * CC];
    const float* as = &a_src[h * CC];
    const float* ad = &a_dst[h * CC];
    float ps = 0.f, pd = 0.f;
    for (int c = lane; c < CC; c += 32) {
        float v = hp[c];
        ps += v * as[c];
        pd += v * ad[c];
    }
    for (int o = 16; o; o >>= 1) {
        ps += __shfl_down_sync(0xffffffffu, ps, o);
        pd += __shfl_down_sync(0xffffffffu, pd, o);
    }
    if (lane == 0) { g_s[gw] = ps; g_d[gw] = pd; }
}

// ---------------- segment softmax (one warp per destination node) ----------
__global__ void softmax_kernel() {
    int warp = (blockIdx.x * blockDim.x + threadIdx.x) >> 5;
    int lane = threadIdx.x & 31;
    if (warp >= NN) return;
    int n  = warp;
    int r0 = g_rowptr[n], r1 = g_rowptr[n + 1];
    for (int h = 0; h < HH; h++) {
        float dn = g_d[n * HH + h];
        float mx = -1e30f;
        for (int p = r0 + lane; p < r1; p += 32) {
            float v = g_s[g_ssrc[p] * HH + h] + dn;
            v = (v > 0.f) ? v : 0.2f * v;
            mx = fmaxf(mx, v);
        }
        for (int o = 16; o; o >>= 1) mx = fmaxf(mx, __shfl_xor_sync(0xffffffffu, mx, o));
        float sum = 0.f;
        for (int p = r0 + lane; p < r1; p += 32) {
            float v = g_s[g_ssrc[p] * HH + h] + dn;
            v = (v > 0.f) ? v : 0.2f * v;
            float ex = __expf(v - mx);
            g_alpha[p * HH + h] = ex;
            sum += ex;
        }
        for (int o = 16; o; o >>= 1) sum += __shfl_xor_sync(0xffffffffu, sum, o);
        float inv = 1.f / (sum + 1e-16f);
        for (int p = r0 + lane; p < r1; p += 32) g_alpha[p * HH + h] *= inv;
    }
}

// ---------------- aggregation + head mean + bias (block per node) ----------
__global__ __launch_bounds__(256)
void aggregate_kernel(const float* __restrict__ bias, float* __restrict__ out) {
    int n   = blockIdx.x;
    int tid = threadIdx.x;            // 256 threads, 3 feature cols each
    __shared__ float sal[HH];
    float a0 = 0.f, a1 = 0.f, a2 = 0.f;
    int r0 = g_rowptr[n], r1 = g_rowptr[n + 1];
    for (int p = r0; p < r1; p++) {
        if (tid < HH) sal[tid] = g_alpha[p * HH + tid];
        __syncthreads();
        const float* hp = &g_h[(size_t)g_ssrc[p] * HC];
#pragma unroll
        for (int h = 0; h < HH; h++) {
            float a = sal[h];
            a0 += a * hp[h * CC + tid];
            a1 += a * hp[h * CC + tid + 256];
            a2 += a * hp[h * CC + tid + 512];
        }
        __syncthreads();
    }
    const float invH = 1.0f / (float)HH;
    out[n * CC + tid]       = a0 * invH + bias[tid];
    out[n * CC + tid + 256] = a1 * invH + bias[tid + 256];
    out[n * CC + tid + 512] = a2 * invH + bias[tid + 512];
}

// ---------------- graph pooling --------------------------------------------
__global__ void pool_zero_kernel() {
    int i = blockIdx.x * blockDim.x + threadIdx.x;
    if (i < GGR * CC) g_pool[i] = 0.f;
    if (i < GGR)      g_cnt[i]  = 0;
}

__global__ void pool_cnt_kernel(const int* __restrict__ batch) {
    int n = blockIdx.x * blockDim.x + threadIdx.x;
    if (n < NN) atomicAdd(&g_cnt[batch[n]], 1);
}

__global__ void pool_acc_kernel(const int* __restrict__ batch,
                                const float* __restrict__ xin) {
    int i = blockIdx.x * blockDim.x + threadIdx.x;
    if (i >= NN * CC) return;
    int n = i / CC, c = i - n * CC;
    atomicAdd(&g_pool[batch[n] * CC + c], xin[i]);
}

// ---------------- final MLP (block per graph) -------------------------------
__global__ __launch_bounds__(128)
void mlp_kernel(const float* __restrict__ w1, const float* __restrict__ b1,
                const float* __restrict__ w2, const float* __restrict__ b2,
                float* __restrict__ out) {
    int gid = blockIdx.x;     // 0..63
    int tid = threadIdx.x;    // 128
    __shared__ float gv[CC];
    __shared__ float z[128];
    float invc = 1.0f / fmaxf((float)g_cnt[gid], 1.0f);
    for (int c = tid; c < CC; c += 128) gv[c] = g_pool[gid * CC + c] * invc;
    __syncthreads();
    float acc = b1[tid];
    for (int k = 0; k < CC; k++) acc += gv[k] * w1[k * 128 + tid];
    z[tid] = fmaxf(acc, 0.f);
    __syncthreads();
    if (tid < 4) {
        float o = b2[tid];
        for (int j = 0; j < 128; j++) o += z[j] * w2[j * 4 + tid];
        out[gid * 4 + tid] = o;
    }
}

// ---------------- launcher ---------------------------------------------------
extern "C" void kernel_launch(void* const* d_in, const int* in_sizes, int n_in,
                              void* d_out, int out_size) {
    const float* x        = (const float*)d_in[0];
    const int*   eidx     = (const int*)  d_in[1];
    const int*   batch    = (const int*)  d_in[2];
    const float* W1       = (const float*)d_in[3];
    const float* a_src1   = (const float*)d_in[4];
    const float* a_dst1   = (const float*)d_in[5];
    const float* b1       = (const float*)d_in[6];
    const float* W2       = (const float*)d_in[7];
    const float* a_src2   = (const float*)d_in[8];
    const float* a_dst2   = (const float*)d_in[9];
    const float* b2       = (const float*)d_in[10];
    const float* mlp_w1   = (const float*)d_in[11];
    const float* mlp_b1   = (const float*)d_in[12];
    const float* mlp_w2   = (const float*)d_in[13];
    const float* mlp_b2   = (const float*)d_in[14];
    float* out = (float*)d_out;

    // pointers to device globals for kernels that take them as args
    float *p_h, *p_x2, *p_y;
    cudaGetSymbolAddress((void**)&p_h,  g_h);
    cudaGetSymbolAddress((void**)&p_x2, g_x2);
    cudaGetSymbolAddress((void**)&p_y,  g_y);

    // --- CSR build (identical every call; cheap) ---
    zero_build_kernel<<<(NN + 255) / 256, 256>>>();
    count_deg_kernel<<<(ETOT + 255) / 256, 256>>>(eidx);
    scan_kernel<<<1, 1024>>>();
    fill_csr_kernel<<<(ETOT + 255) / 256, 256>>>(eidx);

    dim3 ggrid(HC / BN, (NN + BM - 1) / BM);   // 72 x 79

    // --- GAT layer 1 ---
    sgemm_kernel<<<ggrid, 256>>>(x, W1, p_h, NN, CC, HC);
    scores_kernel<<<(NN * HH * 32 + 255) / 256, 256>>>(a_src1, a_dst1);
    softmax_kernel<<<(NN * 32 + 255) / 256, 256>>>();
    aggregate_kernel<<<NN, 256>>>(b1, p_x2);

    // --- GAT layer 2 ---
    sgemm_kernel<<<ggrid, 256>>>(p_x2, W2, p_h, NN, CC, HC);
    scores_kernel<<<(NN * HH * 32 + 255) / 256, 256>>>(a_src2, a_dst2);
    softmax_kernel<<<(NN * 32 + 255) / 256, 256>>>();
    aggregate_kernel<<<NN, 256>>>(b2, p_y);

    // --- pooling + MLP ---
    pool_zero_kernel<<<(GGR * CC + 255) / 256, 256>>>();
    pool_cnt_kernel<<<(NN + 255) / 256, 256>>>(batch);
    pool_acc_kernel<<<(NN * CC + 255) / 256, 256>>>(batch, p_y);
    mlp_kernel<<<GGR, 128>>>(mlp_w1, mlp_b1, mlp_w2, mlp_b2, out);
}

// round 2
// speedup vs baseline: 2.1579x; 2.1579x over previous
#include <cuda_runtime.h>
#include <cuda_bf16.h>

// Problem constants
#define NN   10000          // nodes
#define EE   20000          // edges (without self loops)
#define ETOT 30000          // edges + self loops
#define HH   12             // heads
#define CC   768            // per-head dim (== input feature dim)
#define HC   9216           // H*C
#define GGR  64             // graphs

// ---------------- device scratch (static globals; no runtime alloc) --------
__device__ float g_h[(size_t)NN * HC];     // per-layer node features [N, H*C]
__device__ float g_x2[NN * CC];            // layer-1 output / layer-2 input
__device__ float g_y[NN * CC];             // layer-2 output
__device__ float g_s[NN * HH];             // alpha_src per node/head
__device__ float g_d[NN * HH];             // alpha_dst per node/head
__device__ float g_alpha[ETOT * HH];       // softmax weights, by sorted edge pos
__device__ int   g_indeg[NN];
__device__ int   g_rowptr[NN + 1];
__device__ int   g_fill[NN];
__device__ int   g_ssrc[ETOT];             // source node per CSR position
__device__ float g_pool[GGR * CC];
__device__ int   g_cnt[GGR];

// ---------------- CSR build ------------------------------------------------
__global__ void zero_build_kernel() {
    int i = blockIdx.x * blockDim.x + threadIdx.x;
    if (i < NN) { g_indeg[i] = 0; g_fill[i] = 0; }
}

__global__ void count_deg_kernel(const int* __restrict__ edge_index) {
    int e = blockIdx.x * blockDim.x + threadIdx.x;
    if (e >= ETOT) return;
    int dst = (e < EE) ? edge_index[EE + e] : (e - EE);
    atomicAdd(&g_indeg[dst], 1);
}

__global__ void scan_kernel() {
    __shared__ int sd[1024];
    __shared__ int soff;
    int t = threadIdx.x;
    if (t == 0) { soff = 0; g_rowptr[0] = 0; }
    __syncthreads();
    for (int base = 0; base < NN; base += 1024) {
        int i = base + t;
        int v = (i < NN) ? g_indeg[i] : 0;
        sd[t] = v;
        __syncthreads();
        for (int off = 1; off < 1024; off <<= 1) {
            int tmp = (t >= off) ? sd[t - off] : 0;
            __syncthreads();
            sd[t] += tmp;
            __syncthreads();
        }
        if (i < NN) g_rowptr[i + 1] = soff + sd[t];
        __syncthreads();
        if (t == 0) soff += sd[1023];
        __syncthreads();
    }
}

__global__ void fill_csr_kernel(const int* __restrict__ edge_index) {
    int e = blockIdx.x * blockDim.x + threadIdx.x;
    if (e >= ETOT) return;
    int src = (e < EE) ? edge_index[e]      : (e - EE);
    int dst = (e < EE) ? edge_index[EE + e] : (e - EE);
    int pos = g_rowptr[dst] + atomicAdd(&g_fill[dst], 1);
    g_ssrc[pos] = src;
}

// ---------------- tf32 tensor-core GEMM ------------------------------------
// C[M, 9216] = A[M, 768] * B[768, 9216], fp32 in/out, tf32 mma, fp32 accum.
#define BM   128
#define BN   128
#define BKT  32
#define SPAD 8
#define SSTR (BM + SPAD)                 // 136 (both tiles are 128 wide)
#define ABUF (BKT * SSTR)                // 4352 u32 per stage
#define SMEM_U32 (4 * ABUF)              // A0 A1 B0 B1
#define KITER (CC / BKT)                 // 24

__device__ __forceinline__ unsigned f2tf(float f) {
    unsigned u;
    asm("cvt.rna.tf32.f32 %0, %1;" : "=r"(u) : "f"(f));
    return u;
}

__device__ __forceinline__ void mma_tf32(float* d, const unsigned* a, const unsigned* b) {
    asm volatile(
        "mma.sync.aligned.m16n8k8.row.col.f32.tf32.tf32.f32 "
        "{%0,%1,%2,%3}, {%4,%5,%6,%7}, {%8,%9}, {%0,%1,%2,%3};\n"
        : "+f"(d[0]), "+f"(d[1]), "+f"(d[2]), "+f"(d[3])
        : "r"(a[0]), "r"(a[1]), "r"(a[2]), "r"(a[3]), "r"(b[0]), "r"(b[1]));
}

__global__ __launch_bounds__(256)
void tf32_gemm_kernel(const float* __restrict__ A, const float* __restrict__ B,
                      float* __restrict__ Cm, int M) {
    extern __shared__ unsigned sm[];
    // layout: As[2][BKT][SSTR] then Bs[2][BKT][SSTR]
#define AS(buf, k, m) sm[(buf) * ABUF + (k) * SSTR + (m)]
#define BS(buf, k, n) sm[2 * ABUF + (buf) * ABUF + (k) * SSTR + (n)]

    int tid  = threadIdx.x;
    int brow = blockIdx.y * BM;
    int bcol = blockIdx.x * BN;

    int wid  = tid >> 5, lane = tid & 31;
    int wm   = (wid & 3) * 32;           // warp M offset (4 warps in M)
    int wn   = (wid >> 2) * 64;          // warp N offset (2 warps in N)
    int g    = lane >> 2;                // group id 0..7
    int tg   = lane & 3;                 // thread-in-group 0..3

    // A load mapping: each lane owns row (tid&127), 16 consecutive k
    int a_row   = tid & 127;
    int a_cbase = (tid >> 7) * 16;
    bool a_ok   = (brow + a_row) < M;
    const float* Ap = A + (size_t)(brow + a_row) * CC + a_cbase;

    // B load mapping: row (tid>>5) (+8 per p), 4 consecutive n
    int b_krow = tid >> 5;
    int b_col  = (lane) * 4;
    const float* Bp = B + (size_t)b_krow * HC + bcol + b_col;

    float4 ra[4], rb[4];
    float acc[2][8][4];
#pragma unroll
    for (int i = 0; i < 2; i++)
#pragma unroll
        for (int j = 0; j < 8; j++)
#pragma unroll
            for (int q = 0; q < 4; q++) acc[i][j][q] = 0.f;

    // prologue: load tile 0
#pragma unroll
    for (int p = 0; p < 4; p++) {
        ra[p] = a_ok ? *(const float4*)(Ap + 4 * p)
                     : make_float4(0.f, 0.f, 0.f, 0.f);
        rb[p] = *(const float4*)(Bp + (size_t)(8 * p) * HC);
    }
    {
#pragma unroll
        for (int p = 0; p < 4; p++) {
            int kk = a_cbase + 4 * p;
            AS(0, kk + 0, a_row) = f2tf(ra[p].x);
            AS(0, kk + 1, a_row) = f2tf(ra[p].y);
            AS(0, kk + 2, a_row) = f2tf(ra[p].z);
            AS(0, kk + 3, a_row) = f2tf(ra[p].w);
            uint4 bv;
            bv.x = f2tf(rb[p].x); bv.y = f2tf(rb[p].y);
            bv.z = f2tf(rb[p].z); bv.w = f2tf(rb[p].w);
            *(uint4*)&BS(0, b_krow + 8 * p, b_col) = bv;
        }
    }
    __syncthreads();

    for (int it = 0; it < KITER; it++) {
        int cur = it & 1;
        int k0n = (it + 1) * BKT;
        if (it + 1 < KITER) {
#pragma unroll
            for (int p = 0; p < 4; p++) {
                ra[p] = a_ok ? *(const float4*)(Ap + k0n + 4 * p)
                             : make_float4(0.f, 0.f, 0.f, 0.f);
                rb[p] = *(const float4*)(Bp + (size_t)(k0n + 8 * p) * HC);
            }
        }
        // compute 4 k-steps of 8 from smem stage `cur`
#pragma unroll
        for (int kk = 0; kk < 4; kk++) {
            int kb = kk * 8;
            unsigned af[2][4], bf[8][2];
#pragma unroll
            for (int mi = 0; mi < 2; mi++) {
                int m0 = wm + mi * 16 + g;
                af[mi][0] = AS(cur, kb + tg,     m0);
                af[mi][1] = AS(cur, kb + tg,     m0 + 8);
                af[mi][2] = AS(cur, kb + tg + 4, m0);
                af[mi][3] = AS(cur, kb + tg + 4, m0 + 8);
            }
#pragma unroll
            for (int nj = 0; nj < 8; nj++) {
                int n0 = wn + nj * 8 + g;
                bf[nj][0] = BS(cur, kb + tg,     n0);
                bf[nj][1] = BS(cur, kb + tg + 4, n0);
            }
#pragma unroll
            for (int mi = 0; mi < 2; mi++)
#pragma unroll
                for (int nj = 0; nj < 8; nj++)
                    mma_tf32(acc[mi][nj], af[mi], bf[nj]);
        }
        if (it + 1 < KITER) {
            int nxt = cur ^ 1;
#pragma unroll
            for (int p = 0; p < 4; p++) {
                int kk = a_cbase + 4 * p;
                AS(nxt, kk + 0, a_row) = f2tf(ra[p].x);
                AS(nxt, kk + 1, a_row) = f2tf(ra[p].y);
                AS(nxt, kk + 2, a_row) = f2tf(ra[p].z);
                AS(nxt, kk + 3, a_row) = f2tf(ra[p].w);
                uint4 bv;
                bv.x = f2tf(rb[p].x); bv.y = f2tf(rb[p].y);
                bv.z = f2tf(rb[p].z); bv.w = f2tf(rb[p].w);
                *(uint4*)&BS(nxt, b_krow + 8 * p, b_col) = bv;
            }
        }
        __syncthreads();
    }

    // epilogue
#pragma unroll
    for (int mi = 0; mi < 2; mi++) {
#pragma unroll
        for (int nj = 0; nj < 8; nj++) {
            int r = brow + wm + mi * 16 + g;
            int c = bcol + wn + nj * 8 + 2 * tg;
            if (r < M)
                *(float2*)&Cm[(size_t)r * HC + c] =
                    make_float2(acc[mi][nj][0], acc[mi][nj][1]);
            if (r + 8 < M)
                *(float2*)&Cm[(size_t)(r + 8) * HC + c] =
                    make_float2(acc[mi][nj][2], acc[mi][nj][3]);
        }
    }
#undef AS
#undef BS
}

// ---------------- attention scores s,d (one warp per node/head) ------------
__global__ void scores_kernel(const float* __restrict__ a_src,
                              const float* __restrict__ a_dst) {
    int gw   = (blockIdx.x * blockDim.x + threadIdx.x) >> 5;
    int lane = threadIdx.x & 31;
    if (gw >= NN * HH) return;
    int n = gw / HH, h = gw % HH;
    const float* hp = &g_h[(size_t)n * HC + h * CC];
    const float* as = &a_src[h * CC];
    const float* ad = &a_dst[h * CC];
    float ps = 0.f, pd = 0.f;
    for (int c = lane; c < CC; c += 32) {
        float v = hp[c];
        ps += v * as[c];
        pd += v * ad[c];
    }
    for (int o = 16; o; o >>= 1) {
        ps += __shfl_down_sync(0xffffffffu, ps, o);
        pd += __shfl_down_sync(0xffffffffu, pd, o);
    }
    if (lane == 0) { g_s[gw] = ps; g_d[gw] = pd; }
}

// ---------------- segment softmax (one warp per destination node) ----------
__global__ void softmax_kernel() {
    int warp = (blockIdx.x * blockDim.x + threadIdx.x) >> 5;
    int lane = threadIdx.x & 31;
    if (warp >= NN) return;
    int n  = warp;
    int r0 = g_rowptr[n], r1 = g_rowptr[n + 1];
    for (int h = 0; h < HH; h++) {
        float dn = g_d[n * HH + h];
        float mx = -1e30f;
        for (int p = r0 + lane; p < r1; p += 32) {
            float v = g_s[g_ssrc[p] * HH + h] + dn;
            v = (v > 0.f) ? v : 0.2f * v;
            mx = fmaxf(mx, v);
        }
        for (int o = 16; o; o >>= 1) mx = fmaxf(mx, __shfl_xor_sync(0xffffffffu, mx, o));
        float sum = 0.f;
        for (int p = r0 + lane; p < r1; p += 32) {
            float v = g_s[g_ssrc[p] * HH + h] + dn;
            v = (v > 0.f) ? v : 0.2f * v;
            float ex = __expf(v - mx);
            g_alpha[p * HH + h] = ex;
            sum += ex;
        }
        for (int o = 16; o; o >>= 1) sum += __shfl_xor_sync(0xffffffffu, sum, o);
        float inv = 1.f / (sum + 1e-16f);
        for (int p = r0 + lane; p < r1; p += 32) g_alpha[p * HH + h] *= inv;
    }
}

// ---------------- aggregation + head mean + bias (block per node) ----------
__global__ __launch_bounds__(256)
void aggregate_kernel(const float* __restrict__ bias, float* __restrict__ out) {
    int n   = blockIdx.x;
    int tid = threadIdx.x;            // 256 threads, 3 feature cols each
    __shared__ float sal[HH];
    float a0 = 0.f, a1 = 0.f, a2 = 0.f;
    int r0 = g_rowptr[n], r1 = g_rowptr[n + 1];
    for (int p = r0; p < r1; p++) {
        if (tid < HH) sal[tid] = g_alpha[p * HH + tid];
        __syncthreads();
        const float* hp = &g_h[(size_t)g_ssrc[p] * HC];
#pragma unroll
        for (int h = 0; h < HH; h++) {
            float a = sal[h];
            a0 += a * hp[h * CC + tid];
            a1 += a * hp[h * CC + tid + 256];
            a2 += a * hp[h * CC + tid + 512];
        }
        __syncthreads();
    }
    const float invH = 1.0f / (float)HH;
    out[n * CC + tid]       = a0 * invH + bias[tid];
    out[n * CC + tid + 256] = a1 * invH + bias[tid + 256];
    out[n * CC + tid + 512] = a2 * invH + bias[tid + 512];
}

// ---------------- graph pooling --------------------------------------------
__global__ void pool_zero_kernel() {
    int i = blockIdx.x * blockDim.x + threadIdx.x;
    if (i < GGR * CC) g_pool[i] = 0.f;
    if (i < GGR)      g_cnt[i]  = 0;
}

__global__ void pool_cnt_kernel(const int* __restrict__ batch) {
    int n = blockIdx.x * blockDim.x + threadIdx.x;
    if (n < NN) atomicAdd(&g_cnt[batch[n]], 1);
}

__global__ void pool_acc_kernel(const int* __restrict__ batch,
                                const float* __restrict__ xin) {
    int i = blockIdx.x * blockDim.x + threadIdx.x;
    if (i >= NN * CC) return;
    int n = i / CC, c = i - n * CC;
    atomicAdd(&g_pool[batch[n] * CC + c], xin[i]);
}

// ---------------- final MLP (block per graph) -------------------------------
__global__ __launch_bounds__(128)
void mlp_kernel(const float* __restrict__ w1, const float* __restrict__ b1,
                const float* __restrict__ w2, const float* __restrict__ b2,
                float* __restrict__ out) {
    int gid = blockIdx.x;     // 0..63
    int tid = threadIdx.x;    // 128
    __shared__ float gv[CC];
    __shared__ float z[128];
    float invc = 1.0f / fmaxf((float)g_cnt[gid], 1.0f);
    for (int c = tid; c < CC; c += 128) gv[c] = g_pool[gid * CC + c] * invc;
    __syncthreads();
    float acc = b1[tid];
    for (int k = 0; k < CC; k++) acc += gv[k] * w1[k * 128 + tid];
    z[tid] = fmaxf(acc, 0.f);
    __syncthreads();
    if (tid < 4) {
        float o = b2[tid];
        for (int j = 0; j < 128; j++) o += z[j] * w2[j * 4 + tid];
        out[gid * 4 + tid] = o;
    }
}

// ---------------- launcher ---------------------------------------------------
extern "C" void kernel_launch(void* const* d_in, const int* in_sizes, int n_in,
                              void* d_out, int out_size) {
    const float* x        = (const float*)d_in[0];
    const int*   eidx     = (const int*)  d_in[1];
    const int*   batch    = (const int*)  d_in[2];
    const float* W1       = (const float*)d_in[3];
    const float* a_src1   = (const float*)d_in[4];
    const float* a_dst1   = (const float*)d_in[5];
    const float* b1       = (const float*)d_in[6];
    const float* W2       = (const float*)d_in[7];
    const float* a_src2   = (const float*)d_in[8];
    const float* a_dst2   = (const float*)d_in[9];
    const float* b2       = (const float*)d_in[10];
    const float* mlp_w1   = (const float*)d_in[11];
    const float* mlp_b1   = (const float*)d_in[12];
    const float* mlp_w2   = (const float*)d_in[13];
    const float* mlp_b2   = (const float*)d_in[14];
    float* out = (float*)d_out;

    float *p_h, *p_x2, *p_y;
    cudaGetSymbolAddress((void**)&p_h,  g_h);
    cudaGetSymbolAddress((void**)&p_x2, g_x2);
    cudaGetSymbolAddress((void**)&p_y,  g_y);

    const int smem_bytes = SMEM_U32 * 4;   // 69632
    cudaFuncSetAttribute(tf32_gemm_kernel,
                         cudaFuncAttributeMaxDynamicSharedMemorySize, smem_bytes);

    // --- CSR build (identical every call; cheap) ---
    zero_build_kernel<<<(NN + 255) / 256, 256>>>();
    count_deg_kernel<<<(ETOT + 255) / 256, 256>>>(eidx);
    scan_kernel<<<1, 1024>>>();
    fill_csr_kernel<<<(ETOT + 255) / 256, 256>>>(eidx);

    dim3 ggrid(HC / BN, (NN + BM - 1) / BM);   // 72 x 79

    // --- GAT layer 1 ---
    tf32_gemm_kernel<<<ggrid, 256, smem_bytes>>>(x, W1, p_h, NN);
    scores_kernel<<<(NN * HH * 32 + 255) / 256, 256>>>(a_src1, a_dst1);
    softmax_kernel<<<(NN * 32 + 255) / 256, 256>>>();
    aggregate_kernel<<<NN, 256>>>(b1, p_x2);

    // --- GAT layer 2 ---
    tf32_gemm_kernel<<<ggrid, 256, smem_bytes>>>(p_x2, W2, p_h, NN);
    scores_kernel<<<(NN * HH * 32 + 255) / 256, 256>>>(a_src2, a_dst2);
    softmax_kernel<<<(NN * 32 + 255) / 256, 256>>>();
    aggregate_kernel<<<NN, 256>>>(b2, p_y);

    // --- pooling + MLP ---
    pool_zero_kernel<<<(GGR * CC + 255) / 256, 256>>>();
    pool_cnt_kernel<<<(NN + 255) / 256, 256>>>(batch);
    pool_acc_kernel<<<(NN * CC + 255) / 256, 256>>>(batch, p_y);
    mlp_kernel<<<GGR, 128>>>(mlp_w1, mlp_b1, mlp_w2, mlp_b2, out);
}

// round 4
// speedup vs baseline: 3.6221x; 1.6785x over previous
#include <cuda_runtime.h>
#include <cuda_bf16.h>
#include <cstdint>

// Problem constants
#define NN   10000          // nodes
#define EE   20000          // edges (without self loops)
#define ETOT 30000          // edges + self loops
#define HH   12             // heads
#define CC   768            // per-head dim (== input feature dim)
#define HC   9216           // H*C
#define GGR  64             // graphs

#define MTILES 79           // ceil(10000/128)
#define NTILES 72           // 9216/128
#define FRAG_PER_TILE 98304 // 128*768 floats per (tile, full-K) fragment block

// ---------------- device scratch (static globals; no runtime alloc) --------
__device__ float g_h[(size_t)NN * HC];     // per-layer node features [N, H*C]
__device__ float g_x2[NN * CC];            // layer-1 output / layer-2 input
__device__ float g_y[NN * CC];             // layer-2 output
__device__ float g_Afrag[(size_t)MTILES * FRAG_PER_TILE];  // fragment-major A
__device__ float g_Bfrag[(size_t)NTILES * FRAG_PER_TILE];  // fragment-major W
__device__ float g_s[NN * HH];             // alpha_src per node/head
__device__ float g_d[NN * HH];             // alpha_dst per node/head
__device__ float g_alpha[ETOT * HH];       // softmax weights, by sorted edge pos
__device__ int   g_indeg[NN];
__device__ int   g_rowptr[NN + 1];
__device__ int   g_fill[NN];
__device__ int   g_ssrc[ETOT];             // source node per CSR position
__device__ float g_pool[GGR * CC];
__device__ int   g_cnt[GGR];

// ---------------- helpers ----------------------------------------------------
__device__ __forceinline__ uint32_t smem_u32(const void* p) {
    uint32_t a;
    asm("{ .reg .u64 t; cvta.to.shared.u64 t, %1; cvt.u32.u64 %0, t; }"
        : "=r"(a) : "l"(p));
    return a;
}

__device__ __forceinline__ unsigned f2tf(float f) {
    unsigned u;
    asm("cvt.rna.tf32.f32 %0, %1;" : "=r"(u) : "f"(f));
    return u;
}

__device__ __forceinline__ void mma_tf32(float* d, const unsigned* a,
                                         unsigned b0, unsigned b1) {
    asm volatile(
        "mma.sync.aligned.m16n8k8.row.col.f32.tf32.tf32.f32 "
        "{%0,%1,%2,%3}, {%4,%5,%6,%7}, {%8,%9}, {%0,%1,%2,%3};\n"
        : "+f"(d[0]), "+f"(d[1]), "+f"(d[2]), "+f"(d[3])
        : "r"(a[0]), "r"(a[1]), "r"(a[2]), "r"(a[3]), "r"(b0), "r"(b1));
}

#define CP_ASYNC16(dst, src) \
    asm volatile("cp.async.cg.shared.global [%0], [%1], 16;" :: \
                 "r"(dst), "l"(src) : "memory")
#define CP_COMMIT() asm volatile("cp.async.commit_group;" ::: "memory")
#define CP_WAIT1()  asm volatile("cp.async.wait_group 1;" ::: "memory")
#define CP_WAIT0()  asm volatile("cp.async.wait_group 0;" ::: "memory")

#define LDS128(r0, r1, r2, r3, addr) \
    asm volatile("ld.shared.v4.b32 {%0,%1,%2,%3}, [%4];" \
                 : "=r"(r0), "=r"(r1), "=r"(r2), "=r"(r3) : "r"(addr))

// ---------------- CSR build ------------------------------------------------
__global__ void zero_build_kernel() {
    int i = blockIdx.x * blockDim.x + threadIdx.x;
    if (i < NN) { g_indeg[i] = 0; g_fill[i] = 0; }
}

__global__ void count_deg_kernel(const int* __restrict__ edge_index) {
    int e = blockIdx.x * blockDim.x + threadIdx.x;
    if (e >= ETOT) return;
    int dst = (e < EE) ? edge_index[EE + e] : (e - EE);
    atomicAdd(&g_indeg[dst], 1);
}

__global__ void scan_kernel() {
    __shared__ int sd[1024];
    __shared__ int soff;
    int t = threadIdx.x;
    if (t == 0) { soff = 0; g_rowptr[0] = 0; }
    __syncthreads();
    for (int base = 0; base < NN; base += 1024) {
        int i = base + t;
        int v = (i < NN) ? g_indeg[i] : 0;
        sd[t] = v;
        __syncthreads();
        for (int off = 1; off < 1024; off <<= 1) {
            int tmp = (t >= off) ? sd[t - off] : 0;
            __syncthreads();
            sd[t] += tmp;
            __syncthreads();
        }
        if (i < NN) g_rowptr[i + 1] = soff + sd[t];
        __syncthreads();
        if (t == 0) soff += sd[1023];
        __syncthreads();
    }
}

__global__ void fill_csr_kernel(const int* __restrict__ edge_index) {
    int e = blockIdx.x * blockDim.x + threadIdx.x;
    if (e >= ETOT) return;
    int src = (e < EE) ? edge_index[e]      : (e - EE);
    int dst = (e < EE) ? edge_index[EE + e] : (e - EE);
    int pos = g_rowptr[dst] + atomicAdd(&g_fill[dst], 1);
    g_ssrc[pos] = src;
}

// ---------------- operand packing into fragment-major layout -----------------
// A_frag layout: [mtile][kb8 0..95][m16 0..7][lane 0..31][r 0..3]
//   r0=(m=g,  k=tg) r1=(m=g+8,k=tg) r2=(m=g,k=tg+4) r3=(m=g+8,k=tg+4)
__global__ __launch_bounds__(256)
void prep_A_kernel(const float* __restrict__ src, int M) {
    __shared__ float st[128 * 68];       // 128 rows x 64 cols, pitch 68
    int tid = threadIdx.x, lane = tid & 31, wid = tid >> 5;
    int mtile = blockIdx.x, kgrp = blockIdx.y;   // kgrp covers 64 k
#pragma unroll
    for (int i = 0; i < 8; i++) {
        int idx = tid + i * 256;         // 0..2047
        int row = idx >> 4, c4 = idx & 15;
        int m = mtile * 128 + row;
        float4 v = make_float4(0.f, 0.f, 0.f, 0.f);
        if (m < M) v = *(const float4*)&src[(size_t)m * CC + kgrp * 64 + c4 * 4];
        *(float4*)&st[row * 68 + c4 * 4] = v;
    }
    __syncthreads();
    int g = lane >> 2, tg = lane & 3;
#pragma unroll
    for (int t = 0; t < 8; t++) {
        int fb = wid * 8 + t;
        int kbl = fb & 7, m16 = fb >> 3;
        uint4 o;
        o.x = f2tf(st[(m16 * 16 + g    ) * 68 + kbl * 8 + tg    ]);
        o.y = f2tf(st[(m16 * 16 + g + 8) * 68 + kbl * 8 + tg    ]);
        o.z = f2tf(st[(m16 * 16 + g    ) * 68 + kbl * 8 + tg + 4]);
        o.w = f2tf(st[(m16 * 16 + g + 8) * 68 + kbl * 8 + tg + 4]);
        size_t out = ((size_t)((mtile * 96 + kgrp * 8 + kbl) * 8 + m16)) * 32 + lane;
        ((uint4*)g_Afrag)[out] = o;
    }
}

// B_frag layout: [ntile][kb8][n16 0..7][lane][slot 0..3]
//   slot0=(n8 even, k=tg) slot1=(even, k=tg+4) slot2=(odd, tg) slot3=(odd, tg+4)
__global__ __launch_bounds__(256)
void prep_B_kernel(const float* __restrict__ W) {
    __shared__ float st[64 * 132];       // 64 k-rows x 128 n-cols, pitch 132
    int tid = threadIdx.x, lane = tid & 31, wid = tid >> 5;
    int ntile = blockIdx.x, kgrp = blockIdx.y;
#pragma unroll
    for (int i = 0; i < 8; i++) {
        int idx = tid + i * 256;         // 0..2047
        int row = idx >> 5, c4 = idx & 31;
        float4 v = *(const float4*)&W[(size_t)(kgrp * 64 + row) * HC +
                                      ntile * 128 + c4 * 4];
        *(float4*)&st[row * 132 + c4 * 4] = v;
    }
    __syncthreads();
    int g = lane >> 2, tg = lane & 3;
#pragma unroll
    for (int t = 0; t < 8; t++) {
        int fb = wid * 8 + t;
        int kbl = fb & 7, n16 = fb >> 3;
        uint4 o;
        o.x = f2tf(st[(kbl * 8 + tg    ) * 132 + n16 * 16 + g    ]);
        o.y = f2tf(st[(kbl * 8 + tg + 4) * 132 + n16 * 16 + g    ]);
        o.z = f2tf(st[(kbl * 8 + tg    ) * 132 + n16 * 16 + g + 8]);
        o.w = f2tf(st[(kbl * 8 + tg + 4) * 132 + n16 * 16 + g + 8]);
        size_t out = ((size_t)((ntile * 96 + kgrp * 8 + kbl) * 8 + n16)) * 32 + lane;
        ((uint4*)g_Bfrag)[out] = o;
    }
}

// ---------------- fragment-major tf32 mma.sync GEMM --------------------------
// C[M,9216] = A * W using pre-packed g_Afrag / g_Bfrag.
// CTA 128x128, K chunks of 32 (4 kb8), 2-stage cp.async pipeline.
#define NCHK 24
#define STAGE_BYTES 32768    // 16KB A + 16KB B

__global__ __launch_bounds__(256)
void frag_gemm_kernel(float* __restrict__ Cm, int M) {
    extern __shared__ char smem[];
    const uint32_t sbase = smem_u32(smem);
    const int tid = threadIdx.x, wid = tid >> 5, lane = tid & 31;
    const int mtile = blockIdx.y, ntile = blockIdx.x;
    const char* Abase = (const char*)g_Afrag + (size_t)mtile * FRAG_PER_TILE * 4;
    const char* Bbase = (const char*)g_Bfrag + (size_t)ntile * FRAG_PER_TILE * 4;

    const int g = lane >> 2, tg = lane & 3;
    const int mb16 = (wid & 3) * 2;      // m16 base for this warp (2 blocks)
    const int nb16 = (wid >> 2) * 4;     // n16 base (4 blocks)

    float acc[2][8][4];
#pragma unroll
    for (int i = 0; i < 2; i++)
#pragma unroll
        for (int j = 0; j < 8; j++)
#pragma unroll
            for (int q = 0; q < 4; q++) acc[i][j][q] = 0.f;

#define STAGE_CP(buf, chunk)                                              \
    {                                                                     \
        const char* as = Abase + (size_t)(chunk) * 16384 + tid * 16;      \
        const char* bs = Bbase + (size_t)(chunk) * 16384 + tid * 16;      \
        uint32_t ad = sbase + (buf) * STAGE_BYTES + tid * 16;             \
        uint32_t bd = ad + 16384;                                         \
        _Pragma("unroll")                                                 \
        for (int i = 0; i < 4; i++) {                                     \
            CP_ASYNC16(ad + i * 4096, as + (size_t)i * 4096);             \
            CP_ASYNC16(bd + i * 4096, bs + (size_t)i * 4096);             \
        }                                                                 \
        CP_COMMIT();                                                      \
    }

    STAGE_CP(0, 0)
    STAGE_CP(1, 1)

    for (int it = 0; it < NCHK; it++) {
        if (it + 2 < NCHK) { CP_WAIT1(); } else { CP_WAIT0(); }
        __syncthreads();
        uint32_t sa = sbase + (it & 1) * STAGE_BYTES;
        uint32_t sb = sa + 16384;
#pragma unroll
        for (int k8 = 0; k8 < 4; k8++) {
            unsigned af[2][4], bf[4][4];
#pragma unroll
            for (int mi = 0; mi < 2; mi++) {
                uint32_t a = sa + (uint32_t)(((k8 * 8 + mb16 + mi) * 32 + lane) * 16);
                LDS128(af[mi][0], af[mi][1], af[mi][2], af[mi][3], a);
            }
#pragma unroll
            for (int j = 0; j < 4; j++) {
                uint32_t a = sb + (uint32_t)(((k8 * 8 + nb16 + j) * 32 + lane) * 16);
                LDS128(bf[j][0], bf[j][1], bf[j][2], bf[j][3], a);
            }
#pragma unroll
            for (int mi = 0; mi < 2; mi++)
#pragma unroll
                for (int j = 0; j < 4; j++) {
                    mma_tf32(acc[mi][2 * j],     af[mi], bf[j][0], bf[j][1]);
                    mma_tf32(acc[mi][2 * j + 1], af[mi], bf[j][2], bf[j][3]);
                }
        }
        __syncthreads();
        if (it + 2 < NCHK) STAGE_CP(it & 1, it + 2)
    }

    // epilogue (same fragment->C mapping as validated in R2)
    const int brow = mtile * 128, bcol = ntile * 128;
    const int wm = (wid & 3) * 32, wn = (wid >> 2) * 64;
#pragma unroll
    for (int mi = 0; mi < 2; mi++) {
#pragma unroll
        for (int nj = 0; nj < 8; nj++) {
            int r = brow + wm + mi * 16 + g;
            int c = bcol + wn + nj * 8 + 2 * tg;
            if (r < M)
                *(float2*)&Cm[(size_t)r * HC + c] =
                    make_float2(acc[mi][nj][0], acc[mi][nj][1]);
            if (r + 8 < M)
                *(float2*)&Cm[(size_t)(r + 8) * HC + c] =
                    make_float2(acc[mi][nj][2], acc[mi][nj][3]);
        }
    }
#undef STAGE_CP
}

// ---------------- attention scores s,d (one warp per node/head) ------------
__global__ void scores_kernel(const float* __restrict__ a_src,
                              const float* __restrict__ a_dst) {
    int gw   = (blockIdx.x * blockDim.x + threadIdx.x) >> 5;
    int lane = threadIdx.x & 31;
    if (gw >= NN * HH) return;
    int n = gw / HH, h = gw % HH;
    const float* hp = &g_h[(size_t)n * HC + h * CC];
    const float* as = &a_src[h * CC];
    const float* ad = &a_dst[h * CC];
    float ps = 0.f, pd = 0.f;
    for (int c = lane; c < CC; c += 32) {
        float v = hp[c];
        ps += v * as[c];
        pd += v * ad[c];
    }
    for (int o = 16; o; o >>= 1) {
        ps += __shfl_down_sync(0xffffffffu, ps, o);
        pd += __shfl_down_sync(0xffffffffu, pd, o);
    }
    if (lane == 0) { g_s[gw] = ps; g_d[gw] = pd; }
}

// ---------------- segment softmax (one warp per destination node) ----------
__global__ void softmax_kernel() {
    int warp = (blockIdx.x * blockDim.x + threadIdx.x) >> 5;
    int lane = threadIdx.x & 31;
    if (warp >= NN) return;
    int n  = warp;
    int r0 = g_rowptr[n], r1 = g_rowptr[n + 1];
    for (int h = 0; h < HH; h++) {
        float dn = g_d[n * HH + h];
        float mx = -1e30f;
        for (int p = r0 + lane; p < r1; p += 32) {
            float v = g_s[g_ssrc[p] * HH + h] + dn;
            v = (v > 0.f) ? v : 0.2f * v;
            mx = fmaxf(mx, v);
        }
        for (int o = 16; o; o >>= 1) mx = fmaxf(mx, __shfl_xor_sync(0xffffffffu, mx, o));
        float sum = 0.f;
        for (int p = r0 + lane; p < r1; p += 32) {
            float v = g_s[g_ssrc[p] * HH + h] + dn;
            v = (v > 0.f) ? v : 0.2f * v;
            float ex = __expf(v - mx);
            g_alpha[p * HH + h] = ex;
            sum += ex;
        }
        for (int o = 16; o; o >>= 1) sum += __shfl_xor_sync(0xffffffffu, sum, o);
        float inv = 1.f / (sum + 1e-16f);
        for (int p = r0 + lane; p < r1; p += 32) g_alpha[p * HH + h] *= inv;
    }
}

// ---------------- aggregation + head mean + bias (block per node) ----------
__global__ __launch_bounds__(256)
void aggregate_kernel(const float* __restrict__ bias, float* __restrict__ out) {
    int n   = blockIdx.x;
    int tid = threadIdx.x;            // 256 threads, 3 feature cols each
    __shared__ float sal[HH];
    float a0 = 0.f, a1 = 0.f, a2 = 0.f;
    int r0 = g_rowptr[n], r1 = g_rowptr[n + 1];
    for (int p = r0; p < r1; p++) {
        if (tid < HH) sal[tid] = g_alpha[p * HH + tid];
        __syncthreads();
        const float* hp = &g_h[(size_t)g_ssrc[p] * HC];
#pragma unroll
        for (int h = 0; h < HH; h++) {
            float a = sal[h];
            a0 += a * hp[h * CC + tid];
            a1 += a * hp[h * CC + tid + 256];
            a2 += a * hp[h * CC + tid + 512];
        }
        __syncthreads();
    }
    const float invH = 1.0f / (float)HH;
    out[n * CC + tid]       = a0 * invH + bias[tid];
    out[n * CC + tid + 256] = a1 * invH + bias[tid + 256];
    out[n * CC + tid + 512] = a2 * invH + bias[tid + 512];
}

// ---------------- graph pooling --------------------------------------------
__global__ void pool_zero_kernel() {
    int i = blockIdx.x * blockDim.x + threadIdx.x;
    if (i < GGR * CC) g_pool[i] = 0.f;
    if (i < GGR)      g_cnt[i]  = 0;
}

__global__ void pool_cnt_kernel(const int* __restrict__ batch) {
    int n = blockIdx.x * blockDim.x + threadIdx.x;
    if (n < NN) atomicAdd(&g_cnt[batch[n]], 1);
}

__global__ void pool_acc_kernel(const int* __restrict__ batch,
                                const float* __restrict__ xin) {
    int i = blockIdx.x * blockDim.x + threadIdx.x;
    if (i >= NN * CC) return;
    int n = i / CC, c = i - n * CC;
    atomicAdd(&g_pool[batch[n] * CC + c], xin[i]);
}

// ---------------- final MLP (block per graph) -------------------------------
__global__ __launch_bounds__(128)
void mlp_kernel(const float* __restrict__ w1, const float* __restrict__ b1,
                const float* __restrict__ w2, const float* __restrict__ b2,
                float* __restrict__ out) {
    int gid = blockIdx.x;     // 0..63
    int tid = threadIdx.x;    // 128
    __shared__ float gv[CC];
    __shared__ float z[128];
    float invc = 1.0f / fmaxf((float)g_cnt[gid], 1.0f);
    for (int c = tid; c < CC; c += 128) gv[c] = g_pool[gid * CC + c] * invc;
    __syncthreads();
    float acc = b1[tid];
    for (int k = 0; k < CC; k++) acc += gv[k] * w1[k * 128 + tid];
    z[tid] = fmaxf(acc, 0.f);
    __syncthreads();
    if (tid < 4) {
        float o = b2[tid];
        for (int j = 0; j < 128; j++) o += z[j] * w2[j * 4 + tid];
        out[gid * 4 + tid] = o;
    }
}

// ---------------- launcher ---------------------------------------------------
extern "C" void kernel_launch(void* const* d_in, const int* in_sizes, int n_in,
                              void* d_out, int out_size) {
    const float* x        = (const float*)d_in[0];
    const int*   eidx     = (const int*)  d_in[1];
    const int*   batch    = (const int*)  d_in[2];
    const float* W1       = (const float*)d_in[3];
    const float* a_src1   = (const float*)d_in[4];
    const float* a_dst1   = (const float*)d_in[5];
    const float* b1       = (const float*)d_in[6];
    const float* W2       = (const float*)d_in[7];
    const float* a_src2   = (const float*)d_in[8];
    const float* a_dst2   = (const float*)d_in[9];
    const float* b2       = (const float*)d_in[10];
    const float* mlp_w1   = (const float*)d_in[11];
    const float* mlp_b1   = (const float*)d_in[12];
    const float* mlp_w2   = (const float*)d_in[13];
    const float* mlp_b2   = (const float*)d_in[14];
    float* out = (float*)d_out;

    float *p_h, *p_x2, *p_y;
    cudaGetSymbolAddress((void**)&p_h,  g_h);
    cudaGetSymbolAddress((void**)&p_x2, g_x2);
    cudaGetSymbolAddress((void**)&p_y,  g_y);

    const int gemm_smem = 2 * STAGE_BYTES;     // 65536
    cudaFuncSetAttribute(frag_gemm_kernel,
                         cudaFuncAttributeMaxDynamicSharedMemorySize, gemm_smem);

    // --- CSR build (identical every call; cheap) ---
    zero_build_kernel<<<(NN + 255) / 256, 256>>>();
    count_deg_kernel<<<(ETOT + 255) / 256, 256>>>(eidx);
    scan_kernel<<<1, 1024>>>();
    fill_csr_kernel<<<(ETOT + 255) / 256, 256>>>(eidx);

    dim3 pa_grid(MTILES, 12);
    dim3 pb_grid(NTILES, 12);
    dim3 ggrid(NTILES, MTILES);

    // --- GAT layer 1 ---
    prep_A_kernel<<<pa_grid, 256>>>(x, NN);
    prep_B_kernel<<<pb_grid, 256>>>(W1);
    frag_gemm_kernel<<<ggrid, 256, gemm_smem>>>(p_h, NN);
    scores_kernel<<<(NN * HH * 32 + 255) / 256, 256>>>(a_src1, a_dst1);
    softmax_kernel<<<(NN * 32 + 255) / 256, 256>>>();
    aggregate_kernel<<<NN, 256>>>(b1, p_x2);

    // --- GAT layer 2 ---
    prep_A_kernel<<<pa_grid, 256>>>(p_x2, NN);
    prep_B_kernel<<<pb_grid, 256>>>(W2);
    frag_gemm_kernel<<<ggrid, 256, gemm_smem>>>(p_h, NN);
    scores_kernel<<<(NN * HH * 32 + 255) / 256, 256>>>(a_src2, a_dst2);
    softmax_kernel<<<(NN * 32 + 255) / 256, 256>>>();
    aggregate_kernel<<<NN, 256>>>(b2, p_y);

    // --- pooling + MLP ---
    pool_zero_kernel<<<(GGR * CC + 255) / 256, 256>>>();
    pool_cnt_kernel<<<(NN + 255) / 256, 256>>>(batch);
    pool_acc_kernel<<<(NN * CC + 255) / 256, 256>>>(batch, p_y);
    mlp_kernel<<<GGR, 128>>>(mlp_w1, mlp_b1, mlp_w2, mlp_b2, out);
}